// round 1
// baseline (speedup 1.0000x reference)
#include <cuda_runtime.h>
#include <stdint.h>

// Polar encoder, N=8192, K=4096, frozen = first half.
// Output row = [T(u_row), T(u_row)] where T = 12-stage Arikan transform on 4096 bits.
// One warp per row; bits packed 128 x u32 (4 regs/lane), word w -> lane (w&31), reg (w>>5).

__global__ __launch_bounds__(256) void polar_encode_kernel(
    const float* __restrict__ u,   // [rows, 4096] bits as float {0,1}
    uint4* __restrict__ out,       // [rows, 8192] floats, viewed as uint4 (2048 per row)
    int rows)
{
    const unsigned FULL = 0xffffffffu;
    int warp = (int)((blockIdx.x * blockDim.x + threadIdx.x) >> 5);
    int lane = threadIdx.x & 31;
    if (warp >= rows) return;

    const float* ur = u + (size_t)warp * 4096;
    unsigned r[4];

    // ---- pack: 128 coalesced 128B loads + ballots ----
    #pragma unroll
    for (int j = 0; j < 4; j++) {
        unsigned w = 0;
        #pragma unroll
        for (int k = 0; k < 32; k++) {
            float v = ur[(j * 32 + k) * 32 + lane];
            unsigned m = __ballot_sync(FULL, v > 0.5f);
            if (lane == k) w = m;   // word (j*32+k): owner lane = k, reg = j
        }
        r[j] = w;
    }

    // ---- stages s=0..4: within-word butterflies ----
    #pragma unroll
    for (int j = 0; j < 4; j++) {
        unsigned x = r[j];
        x ^= (x >> 1)  & 0x55555555u;
        x ^= (x >> 2)  & 0x33333333u;
        x ^= (x >> 4)  & 0x0F0F0F0Fu;
        x ^= (x >> 8)  & 0x00FF00FFu;
        x ^= (x >> 16) & 0x0000FFFFu;
        r[j] = x;
    }

    // ---- stages s=5..9: cross-lane (word stride 1,2,4,8,16 == lane stride) ----
    #pragma unroll
    for (int k = 0; k < 5; k++) {
        unsigned keep = (((lane >> k) & 1) == 0) ? 0xffffffffu : 0u;
        #pragma unroll
        for (int j = 0; j < 4; j++) {
            unsigned p = __shfl_xor_sync(FULL, r[j], 1 << k);
            r[j] ^= (p & keep);
        }
    }

    // ---- stage s=10 (word stride 32: reg bit 0), s=11 (stride 64: reg bit 1) ----
    r[0] ^= r[1]; r[2] ^= r[3];
    r[0] ^= r[2]; r[1] ^= r[3];

    // ---- unpack + duplicate halves, uint4 (=float4) stores ----
    uint4* o = out + (size_t)warp * 2048;   // 8192 floats / 4
    #pragma unroll
    for (int i = 0; i < 32; i++) {
        int j = i >> 3;                               // uniform reg index
        int src = (i * 4 + (lane >> 3)) & 31;         // owner lane of word wi = i*4 + (lane>>3)
        unsigned ww = __shfl_sync(FULL, r[j], src);
        unsigned nib = (ww >> ((lane & 7) * 4)) & 0xFu;
        uint4 v;
        v.x = (nib & 1u)        * 0x3f800000u;
        v.y = ((nib >> 1) & 1u) * 0x3f800000u;
        v.z = ((nib >> 2) & 1u) * 0x3f800000u;
        v.w = ((nib >> 3) & 1u) * 0x3f800000u;
        int idx = i * 32 + lane;                       // uint4 index within first half
        o[idx]        = v;                             // first half
        o[idx + 1024] = v;                             // duplicated second half
    }
}

extern "C" void kernel_launch(void* const* d_in, const int* in_sizes, int n_in,
                              void* d_out, int out_size)
{
    const float* u = (const float*)d_in[0];     // [BS, 4096] float {0,1}
    int rows = in_sizes[0] / 4096;              // BS = 8192
    uint4* out = (uint4*)d_out;                 // [BS, 8192] float32

    int threads = 256;                          // 8 warps/block, 1 warp per row
    int blocks = (rows * 32 + threads - 1) / threads;
    polar_encode_kernel<<<blocks, threads>>>(u, out, rows);
}

// round 4
// speedup vs baseline: 1.0064x; 1.0064x over previous
#include <cuda_runtime.h>
#include <stdint.h>

// Polar encoder, N=8192, K=4096, frozen = first half.
// Output row = [T(u_row), T(u_row)] where T = 12-stage Arikan transform on 4096 bits.
// One warp per row; bits packed 128 x u32 (4 regs/lane), word w -> lane (w&31), reg (w>>5).

__global__ __launch_bounds__(128) void polar_encode_kernel(
    const float* __restrict__ u,   // [rows, 4096] bits as float {0,1}
    uint4* __restrict__ out,       // [rows, 8192] floats, viewed as uint4 (2048 per row)
    int rows)
{
    const unsigned FULL = 0xffffffffu;
    int warp = (int)((blockIdx.x * blockDim.x + threadIdx.x) >> 5);
    int lane = threadIdx.x & 31;

    const float* ur = u + (size_t)warp * 4096;
    unsigned r[4];

    // ---- pack: 128 coalesced 128B streaming loads + ballots ----
    #pragma unroll
    for (int j = 0; j < 4; j++) {
        unsigned w = 0;
        #pragma unroll
        for (int k = 0; k < 32; k++) {
            float v = __ldcs(ur + (j * 32 + k) * 32 + lane);
            unsigned m = __ballot_sync(FULL, v > 0.5f);
            if (lane == k) w = m;   // word (j*32+k): owner lane = k, reg = j
        }
        r[j] = w;
    }

    // ---- stages s=0..4: within-word butterflies ----
    #pragma unroll
    for (int j = 0; j < 4; j++) {
        unsigned x = r[j];
        x ^= (x >> 1)  & 0x55555555u;
        x ^= (x >> 2)  & 0x33333333u;
        x ^= (x >> 4)  & 0x0F0F0F0Fu;
        x ^= (x >> 8)  & 0x00FF00FFu;
        x ^= (x >> 16) & 0x0000FFFFu;
        r[j] = x;
    }

    // ---- stages s=5..9: cross-lane (word stride 1,2,4,8,16 == lane stride) ----
    #pragma unroll
    for (int k = 0; k < 5; k++) {
        unsigned keep = (((lane >> k) & 1) == 0) ? 0xffffffffu : 0u;
        #pragma unroll
        for (int j = 0; j < 4; j++) {
            unsigned p = __shfl_xor_sync(FULL, r[j], 1 << k);
            r[j] ^= (p & keep);
        }
    }

    // ---- stage s=10 (word stride 32: reg bit 0), s=11 (stride 64: reg bit 1) ----
    r[0] ^= r[1]; r[2] ^= r[3];
    r[0] ^= r[2]; r[1] ^= r[3];

    // ---- unpack + duplicate halves, streaming uint4 (=float4) stores ----
    uint4* o = out + (size_t)warp * 2048;   // 8192 floats / 4
    #pragma unroll
    for (int i = 0; i < 32; i++) {
        int j = i >> 3;                               // uniform reg index
        int src = (i * 4 + (lane >> 3)) & 31;         // owner lane of word wi = i*4 + (lane>>3)
        unsigned ww = __shfl_sync(FULL, r[j], src);
        unsigned nib = (ww >> ((lane & 7) * 4)) & 0xFu;
        uint4 v;
        v.x = (nib & 1u)        * 0x3f800000u;
        v.y = ((nib >> 1) & 1u) * 0x3f800000u;
        v.z = ((nib >> 2) & 1u) * 0x3f800000u;
        v.w = ((nib >> 3) & 1u) * 0x3f800000u;
        int idx = i * 32 + lane;                       // uint4 index within first half
        __stcs(o + idx,        v);                     // first half
        __stcs(o + idx + 1024, v);                     // duplicated second half
    }
}

extern "C" void kernel_launch(void* const* d_in, const int* in_sizes, int n_in,
                              void* d_out, int out_size)
{
    const float* u = (const float*)d_in[0];     // [BS, 4096] float {0,1}
    int rows = in_sizes[0] / 4096;              // BS = 8192
    uint4* out = (uint4*)d_out;                 // [BS, 8192] float32

    int threads = 128;                          // 4 warps/block, 1 warp per row
    int blocks = (rows * 32 + threads - 1) / threads;   // 2048 blocks, exact
    polar_encode_kernel<<<blocks, threads>>>(u, out, rows);
}

// round 5
// speedup vs baseline: 1.0111x; 1.0046x over previous
#include <cuda_runtime.h>
#include <stdint.h>

// Polar encoder, N=8192, K=4096, frozen = first half.
// Output row = [T(u_row), T(u_row)], T = 12-stage Arikan transform on 4096 bits.
// One warp per row. Bit layout: global bit i = q*1024 + p*128 + lane*4 + j
//   j = bits 0-1  -> float4 component   (in-word distance 1,2)
//   l = bits 2-6  -> lane               (shfl_xor 1,2,4,8,16)
//   p = bits 7-9  -> nibble slot in word (in-word distance 4,8,16)
//   q = bits 10-11-> register index      (register pairs)
// Pack and unpack are pure per-lane ops: no ballots, no shfls outside the butterfly.

__global__ __launch_bounds__(128) void polar_encode_kernel(
    const float* __restrict__ u,   // [rows, 4096] bits as float {0,1}
    uint4* __restrict__ out,       // [rows, 8192] floats viewed as uint4
    int rows)
{
    const unsigned FULL = 0xffffffffu;
    int warp = (int)((blockIdx.x * blockDim.x + threadIdx.x) >> 5);
    int lane = threadIdx.x & 31;

    const float4* uv = (const float4*)u + (size_t)warp * 1024;  // 4096 floats
    unsigned r[4] = {0u, 0u, 0u, 0u};

    // ---- pack: 32 independent 512B coalesced float4 loads per warp ----
    #pragma unroll
    for (int t = 0; t < 32; t++) {
        float4 v = __ldcs((const float4*)(uv + t * 32 + lane));
        unsigned nib = (v.x > 0.5f ? 1u : 0u)
                     | (v.y > 0.5f ? 2u : 0u)
                     | (v.z > 0.5f ? 4u : 0u)
                     | (v.w > 0.5f ? 8u : 0u);
        r[t >> 3] |= nib << ((t & 7) * 4);
    }

    // ---- stages s=0,1: j bits (in-word distance 1,2) ----
    #pragma unroll
    for (int jq = 0; jq < 4; jq++) {
        unsigned x = r[jq];
        x ^= (x >> 1) & 0x55555555u;
        x ^= (x >> 2) & 0x33333333u;
        r[jq] = x;
    }

    // ---- stages s=2..6: lane bits (shfl_xor 1,2,4,8,16) ----
    #pragma unroll
    for (int k = 0; k < 5; k++) {
        unsigned keep = (((lane >> k) & 1) == 0) ? 0xffffffffu : 0u;
        #pragma unroll
        for (int jq = 0; jq < 4; jq++) {
            unsigned p = __shfl_xor_sync(FULL, r[jq], 1 << k);
            r[jq] ^= (p & keep);
        }
    }

    // ---- stages s=7,8,9: p bits (in-word distance 4,8,16) ----
    #pragma unroll
    for (int jq = 0; jq < 4; jq++) {
        unsigned x = r[jq];
        x ^= (x >> 4)  & 0x0F0F0F0Fu;
        x ^= (x >> 8)  & 0x00FF00FFu;
        x ^= (x >> 16) & 0x0000FFFFu;
        r[jq] = x;
    }

    // ---- stages s=10,11: q bits (register pairs) ----
    r[0] ^= r[1]; r[2] ^= r[3];
    r[0] ^= r[2]; r[1] ^= r[3];

    // ---- unpack + duplicate halves: pure per-lane nibble -> float4 stores ----
    uint4* o = out + (size_t)warp * 2048;   // 8192 floats / 4
    #pragma unroll
    for (int t = 0; t < 32; t++) {
        unsigned nib = (r[t >> 3] >> ((t & 7) * 4)) & 0xFu;
        uint4 v;
        v.x = (nib & 1u)        * 0x3f800000u;
        v.y = ((nib >> 1) & 1u) * 0x3f800000u;
        v.z = ((nib >> 2) & 1u) * 0x3f800000u;
        v.w = ((nib >> 3) & 1u) * 0x3f800000u;
        int idx = t * 32 + lane;
        __stcs(o + idx,        v);          // first half
        __stcs(o + idx + 1024, v);          // duplicated second half
    }
}

extern "C" void kernel_launch(void* const* d_in, const int* in_sizes, int n_in,
                              void* d_out, int out_size)
{
    const float* u = (const float*)d_in[0];     // [BS, 4096] float {0,1}
    int rows = in_sizes[0] / 4096;              // BS = 8192
    uint4* out = (uint4*)d_out;                 // [BS, 8192] float32

    int threads = 128;                          // 4 warps/block, 1 warp per row
    int blocks = (rows * 32 + threads - 1) / threads;   // 2048 blocks, exact
    polar_encode_kernel<<<blocks, threads>>>(u, out, rows);
}